// round 2
// baseline (speedup 1.0000x reference)
#include <cuda_runtime.h>
#include <cuda_bf16.h>
#include <cstddef>

#define EPSF 0.01f
#define NU 256
#define NB 64
#define TS 2048

// Module-load-time scratch (no runtime allocation)
__device__ float g_xu[(size_t)NB * TS * NU];   // x@U + b, [b][t][u]   (128 MB)
__device__ float g_AeT[NU * NU];               // EPS*A, transposed: g_AeT[u][k] = EPS*A[k][u]
__device__ float g_WT [NU * NU];               // W,     transposed: g_WT [u][k] = W[k][u]

// ---------------- packed fp32x2 helpers ----------------
static __device__ __forceinline__ unsigned long long fma2(unsigned long long a,
                                                          unsigned long long b,
                                                          unsigned long long c) {
    unsigned long long d;
    asm("fma.rn.f32x2 %0, %1, %2, %3;" : "=l"(d) : "l"(a), "l"(b), "l"(c));
    return d;
}
static __device__ __forceinline__ unsigned long long pk2(float lo, float hi) {
    unsigned long long d;
    asm("mov.b64 %0, {%1, %2};" : "=l"(d) : "f"(lo), "f"(hi));
    return d;
}
static __device__ __forceinline__ void upk2(unsigned long long v, float& lo, float& hi) {
    asm("mov.b64 {%0, %1}, %2;" : "=f"(lo), "=f"(hi) : "l"(v));
}
static __device__ __forceinline__ unsigned su32(const void* p) {
    unsigned r;
    asm("{ .reg .u64 t; cvta.to.shared.u64 t, %1; cvt.u32.u64 %0, t; }" : "=r"(r) : "l"(p));
    return r;
}

// ---------------- kernel 1: build weight matrices ----------------
// A = B - 0.6*B^T - 0.01*I ; W = C - 0.6*C^T - 0.01*I  (BETA=0.8 algebra folded)
// Stored transposed so (h@A)[u] = sum_k h[k]*AeT[u][k] reads contiguous k.
// EPS folded into Ae.
__global__ void prep_kernel(const float* __restrict__ C, const float* __restrict__ B) {
    int u = blockIdx.x;
    int k = threadIdx.x;
    float dg = (u == k) ? 0.01f : 0.0f;
    g_AeT[u * NU + k] = EPSF * (B[k * NU + u] - 0.6f * B[u * NU + k] - dg);
    g_WT [u * NU + k] =        (C[k * NU + u] - 0.6f * C[u * NU + k] - dg);
}

// ---------------- kernel 2: xu = X @ U + bias ----------------
// X: [131072, 256] row-major, U: [256, 256] row-major.
// BM=128, BN=128, BK=32, 256 threads, 8x8 micro-tile, fp32x2 packed FMA.
__global__ __launch_bounds__(256) void xu_kernel(const float* __restrict__ X,
                                                 const float* __restrict__ U,
                                                 const float* __restrict__ bias) {
    __shared__ __align__(16) float Xs[32][132];   // [k][m] padded
    __shared__ __align__(16) float Us[32][132];   // [k][n] padded

    int tid = threadIdx.x;
    int m0 = blockIdx.x * 128;
    int n0 = blockIdx.y * 128;
    int tx = tid & 15;    // n group: cols tx*8 .. +7
    int ty = tid >> 4;    // m group: rows ty*8 .. +7

    unsigned long long acc[8][4];
#pragma unroll
    for (int i = 0; i < 8; i++)
#pragma unroll
        for (int j = 0; j < 4; j++) acc[i][j] = 0ULL;

    for (int kt = 0; kt < 256; kt += 32) {
        // X tile -> Xs[k][m] (transposed store)
#pragma unroll
        for (int i = 0; i < 4; i++) {
            int f = tid + i * 256;          // 1024 float4 slots: 128 m x 8 k4
            int m = f >> 3;
            int k4 = (f & 7) * 4;
            float4 v = *(const float4*)&X[(size_t)(m0 + m) * 256 + kt + k4];
            Xs[k4 + 0][m] = v.x;
            Xs[k4 + 1][m] = v.y;
            Xs[k4 + 2][m] = v.z;
            Xs[k4 + 3][m] = v.w;
        }
        // U tile -> Us[k][n]
#pragma unroll
        for (int i = 0; i < 4; i++) {
            int f = tid + i * 256;          // 32 k x 32 n4
            int k = f >> 5;
            int n4 = (f & 31) * 4;
            float4 v = *(const float4*)&U[(size_t)(kt + k) * 256 + n0 + n4];
            *(float4*)&Us[k][n4] = v;
        }
        __syncthreads();

#pragma unroll
        for (int kk = 0; kk < 32; kk++) {
            float a[8];
            *(float4*)&a[0] = *(const float4*)&Xs[kk][ty * 8];
            *(float4*)&a[4] = *(const float4*)&Xs[kk][ty * 8 + 4];
            ulonglong2 b01 = *(const ulonglong2*)&Us[kk][tx * 8];
            ulonglong2 b23 = *(const ulonglong2*)&Us[kk][tx * 8 + 4];
#pragma unroll
            for (int mi = 0; mi < 8; mi++) {
                unsigned long long ad = pk2(a[mi], a[mi]);
                acc[mi][0] = fma2(ad, b01.x, acc[mi][0]);
                acc[mi][1] = fma2(ad, b01.y, acc[mi][1]);
                acc[mi][2] = fma2(ad, b23.x, acc[mi][2]);
                acc[mi][3] = fma2(ad, b23.y, acc[mi][3]);
            }
        }
        __syncthreads();
    }

    float bv[8];
#pragma unroll
    for (int j = 0; j < 8; j++) bv[j] = bias[n0 + tx * 8 + j];
#pragma unroll
    for (int mi = 0; mi < 8; mi++) {
        float* orow = &g_xu[(size_t)(m0 + ty * 8 + mi) * 256 + n0 + tx * 8];
#pragma unroll
        for (int ni = 0; ni < 4; ni++) {
            float lo, hi;
            upk2(acc[mi][ni], lo, hi);
            float2 v = make_float2(lo + bv[2 * ni], hi + bv[2 * ni + 1]);
            *(float2*)&orow[2 * ni] = v;
        }
    }
}

// ---------------- kernel 3: the recurrence ----------------
// 16 clusters x 8 CTAs = 128 CTAs. Cluster c owns batches [4c,4c+4).
// CTA rank r owns units [32r, 32r+32); its weight slices live in registers.
// h state (256 units x 4 batches), double buffered, replicated in every CTA's
// smem; producers broadcast new h via st.shared::cluster; one cluster barrier/step.
__global__ void __launch_bounds__(512, 1) __cluster_dims__(8, 1, 1)
rec_kernel(float* __restrict__ out) {
    __shared__ __align__(16) float h_s[2][4][NU];        // [buf][b][k]  8 KB
    __shared__ __align__(16) float red_s[16][8][32];     // [ks][b*2+m][u] 16 KB

    int tid = threadIdx.x;
    int u   = tid & 31;     // unit within CTA slice
    int ks  = tid >> 5;     // k-split 0..15, each 16 k
    unsigned rank;
    asm("mov.u32 %0, %%cluster_ctarank;" : "=r"(rank));
    int bg = (int)(blockIdx.x >> 3);          // cluster id = batch group
    int ug = (int)rank * 32 + u;              // global unit
    int k0 = ks * 16;

    // Load weight slices into registers as native k-pairs (f32x2)
    unsigned long long wA[8], wW[8];
    {
        const unsigned long long* pA = (const unsigned long long*)(g_AeT + (size_t)ug * NU + k0);
        const unsigned long long* pW = (const unsigned long long*)(g_WT  + (size_t)ug * NU + k0);
#pragma unroll
        for (int i = 0; i < 8; i++) { wA[i] = pA[i]; wW[i] = pW[i]; }
    }

    // Zero read buffer for t=0 (h0 = 0)
    for (int i = tid; i < 4 * NU; i += 512) ((float*)h_s[0])[i] = 0.0f;

    // Consumer setup (first 128 threads: one (u, b) output each)
    int cb = tid >> 5;                 // 0..3 for tid<128
    int cu = tid & 31;
    const float* xu_p = g_xu + ((size_t)(bg * 4 + cb)) * TS * NU + ((int)rank * 32 + cu);
    float* out_p      = out  + ((size_t)(bg * 4 + cb)) * TS * NU + ((int)rank * 32 + cu);

    // Precompute DSMEM addresses of h_s[buf][cb][ug] in all 8 cluster CTAs
    unsigned ra[2][8];
    if (tid < 128) {
#pragma unroll
        for (int bb = 0; bb < 2; bb++) {
            unsigned la = su32(&h_s[bb][cb][(int)rank * 32 + cu]);
#pragma unroll
            for (int r = 0; r < 8; r++) {
                asm("mapa.shared::cluster.u32 %0, %1, %2;" : "=r"(ra[bb][r]) : "r"(la), "r"(r));
            }
        }
    }
    __syncthreads();

    for (int t = 0; t < TS; t++) {
        int rb = t & 1;
        int wb = rb ^ 1;

        // Prefetch xu[t] (consumers) — latency hidden under the FMA phase
        float xu_v = 0.0f;
        if (tid < 128) xu_v = __ldg(xu_p + (size_t)t * NU);

        // ---- FMA phase: partial dot products over this thread's k range ----
        unsigned long long accA[4], accW[4];
#pragma unroll
        for (int b = 0; b < 4; b++) { accA[b] = 0ULL; accW[b] = 0ULL; }
#pragma unroll
        for (int b = 0; b < 4; b++) {
            const ulonglong2* hp = (const ulonglong2*)&h_s[rb][b][k0];
            unsigned long long hk[8];
#pragma unroll
            for (int j = 0; j < 4; j++) {           // broadcast LDS.128 across warp
                ulonglong2 v = hp[j];
                hk[2 * j] = v.x; hk[2 * j + 1] = v.y;
            }
#pragma unroll
            for (int kk = 0; kk < 8; kk++) {
                accA[b] = fma2(wA[kk], hk[kk], accA[b]);
                accW[b] = fma2(wW[kk], hk[kk], accW[b]);
            }
        }
        // Store partials (conflict-free: lanes u consecutive)
#pragma unroll
        for (int b = 0; b < 4; b++) {
            float lo, hi;
            upk2(accA[b], lo, hi); red_s[ks][b * 2 + 0][u] = lo + hi;
            upk2(accW[b], lo, hi); red_s[ks][b * 2 + 1][u] = lo + hi;
        }
        __syncthreads();

        // ---- Consumer phase: reduce 16 k-splits, update h, broadcast ----
        if (tid < 128) {
            float sA = 0.0f, sW = 0.0f;
#pragma unroll
            for (int kss = 0; kss < 16; kss++) {
                sA += red_s[kss][cb * 2 + 0][cu];
                sW += red_s[kss][cb * 2 + 1][cu];
            }
            float hold = h_s[rb][cb][(int)rank * 32 + cu];
            float hnew = hold + sA + EPSF * tanhf(sW + xu_v);
            out_p[(size_t)t * NU] = hnew;
            // Broadcast to all 8 CTAs' write buffer (incl. self)
#pragma unroll
            for (int r = 0; r < 8; r++) {
                asm volatile("st.shared::cluster.f32 [%0], %1;"
                             :: "r"(ra[wb][r]), "f"(hnew) : "memory");
            }
        }

        // One cluster barrier per step: release prior writes / acquire peers'
        asm volatile("barrier.cluster.arrive.aligned;" ::: "memory");
        asm volatile("barrier.cluster.wait.aligned;" ::: "memory");
    }
}

extern "C" void kernel_launch(void* const* d_in, const int* in_sizes, int n_in,
                              void* d_out, int out_size) {
    const float* x = (const float*)d_in[0];
    const float* C = (const float*)d_in[1];
    const float* B = (const float*)d_in[2];
    const float* U = (const float*)d_in[3];
    const float* b = (const float*)d_in[4];
    float* out = (float*)d_out;

    prep_kernel<<<NU, NU>>>(C, B);
    xu_kernel<<<dim3((NB * TS) / 128, NU / 128), 256>>>(x, U, b);
    rec_kernel<<<128, 512>>>(out);
}

// round 4
// speedup vs baseline: 1.7114x; 1.7114x over previous
#include <cuda_runtime.h>
#include <cuda_bf16.h>
#include <cstddef>

#define EPSF 0.01f
#define NU 256
#define NB 64
#define TS 2048

// Module-load-time scratch (no runtime allocation)
__device__ float g_xu[(size_t)NB * TS * NU];   // x@U + b, [b][t][u]
__device__ float g_AeT[NU * NU];               // EPS*A, transposed: g_AeT[u][k] = EPS*A[k][u]
__device__ float g_WT [NU * NU];               // W,     transposed: g_WT [u][k] = W[k][u]

// ---------------- packed fp32x2 helpers ----------------
static __device__ __forceinline__ unsigned long long fma2(unsigned long long a,
                                                          unsigned long long b,
                                                          unsigned long long c) {
    unsigned long long d;
    asm("fma.rn.f32x2 %0, %1, %2, %3;" : "=l"(d) : "l"(a), "l"(b), "l"(c));
    return d;
}
static __device__ __forceinline__ unsigned long long pk2(float lo, float hi) {
    unsigned long long d;
    asm("mov.b64 %0, {%1, %2};" : "=l"(d) : "f"(lo), "f"(hi));
    return d;
}
static __device__ __forceinline__ void upk2(unsigned long long v, float& lo, float& hi) {
    asm("mov.b64 {%0, %1}, %2;" : "=f"(lo), "=f"(hi) : "l"(v));
}
static __device__ __forceinline__ unsigned su32(const void* p) {
    unsigned r;
    asm("{ .reg .u64 t; cvta.to.shared.u64 t, %1; cvt.u32.u64 %0, t; }" : "=r"(r) : "l"(p));
    return r;
}
static __device__ __forceinline__ void mbar_init(unsigned m, unsigned cnt) {
    asm volatile("mbarrier.init.shared.b64 [%0], %1;" :: "r"(m), "r"(cnt) : "memory");
}
static __device__ __forceinline__ void mbar_expect(unsigned m, unsigned bytes) {
    asm volatile("mbarrier.arrive.expect_tx.shared.b64 _, [%0], %1;" :: "r"(m), "r"(bytes) : "memory");
}
static __device__ __forceinline__ void mbar_wait(unsigned m, unsigned phase) {
    unsigned done;
    asm volatile(
        "{\n\t.reg .pred p;\n\t"
        "mbarrier.try_wait.parity.acquire.cluster.shared::cta.b64 p, [%1], %2;\n\t"
        "selp.b32 %0, 1, 0, p;\n\t}"
        : "=r"(done) : "r"(m), "r"(phase) : "memory");
    while (!done) {
        asm volatile(
            "{\n\t.reg .pred p;\n\t"
            "mbarrier.try_wait.parity.acquire.cluster.shared::cta.b64 p, [%1], %2, 0x989680;\n\t"
            "selp.b32 %0, 1, 0, p;\n\t}"
            : "=r"(done) : "r"(m), "r"(phase) : "memory");
    }
}
static __device__ __forceinline__ void st_async_remote(unsigned raddr, float v, unsigned rmbar) {
    asm volatile("st.async.shared::cluster.mbarrier::complete_tx::bytes.u32 [%0], %1, [%2];"
                 :: "r"(raddr), "r"(__float_as_uint(v)), "r"(rmbar) : "memory");
}

// ---------------- kernel 1: build weight matrices ----------------
__global__ void prep_kernel(const float* __restrict__ C, const float* __restrict__ B) {
    int u = blockIdx.x;
    int k = threadIdx.x;
    float dg = (u == k) ? 0.01f : 0.0f;
    g_AeT[u * NU + k] = EPSF * (B[k * NU + u] - 0.6f * B[u * NU + k] - dg);
    g_WT [u * NU + k] =        (C[k * NU + u] - 0.6f * C[u * NU + k] - dg);
}

// ---------------- kernel 2: xu = X @ U + bias ----------------
__global__ __launch_bounds__(256) void xu_kernel(const float* __restrict__ X,
                                                 const float* __restrict__ U,
                                                 const float* __restrict__ bias) {
    __shared__ __align__(16) float Xs[32][132];
    __shared__ __align__(16) float Us[32][132];

    int tid = threadIdx.x;
    int m0 = blockIdx.x * 128;
    int n0 = blockIdx.y * 128;
    int tx = tid & 15;
    int ty = tid >> 4;

    unsigned long long acc[8][4];
#pragma unroll
    for (int i = 0; i < 8; i++)
#pragma unroll
        for (int j = 0; j < 4; j++) acc[i][j] = 0ULL;

    for (int kt = 0; kt < 256; kt += 32) {
#pragma unroll
        for (int i = 0; i < 4; i++) {
            int f = tid + i * 256;
            int m = f >> 3;
            int k4 = (f & 7) * 4;
            float4 v = *(const float4*)&X[(size_t)(m0 + m) * 256 + kt + k4];
            Xs[k4 + 0][m] = v.x;
            Xs[k4 + 1][m] = v.y;
            Xs[k4 + 2][m] = v.z;
            Xs[k4 + 3][m] = v.w;
        }
#pragma unroll
        for (int i = 0; i < 4; i++) {
            int f = tid + i * 256;
            int k = f >> 5;
            int n4 = (f & 31) * 4;
            float4 v = *(const float4*)&U[(size_t)(kt + k) * 256 + n0 + n4];
            *(float4*)&Us[k][n4] = v;
        }
        __syncthreads();

#pragma unroll
        for (int kk = 0; kk < 32; kk++) {
            float a[8];
            *(float4*)&a[0] = *(const float4*)&Xs[kk][ty * 8];
            *(float4*)&a[4] = *(const float4*)&Xs[kk][ty * 8 + 4];
            ulonglong2 b01 = *(const ulonglong2*)&Us[kk][tx * 8];
            ulonglong2 b23 = *(const ulonglong2*)&Us[kk][tx * 8 + 4];
#pragma unroll
            for (int mi = 0; mi < 8; mi++) {
                unsigned long long ad = pk2(a[mi], a[mi]);
                acc[mi][0] = fma2(ad, b01.x, acc[mi][0]);
                acc[mi][1] = fma2(ad, b01.y, acc[mi][1]);
                acc[mi][2] = fma2(ad, b23.x, acc[mi][2]);
                acc[mi][3] = fma2(ad, b23.y, acc[mi][3]);
            }
        }
        __syncthreads();
    }

    float bv[8];
#pragma unroll
    for (int j = 0; j < 8; j++) bv[j] = bias[n0 + tx * 8 + j];
#pragma unroll
    for (int mi = 0; mi < 8; mi++) {
        float* orow = &g_xu[(size_t)(m0 + ty * 8 + mi) * 256 + n0 + tx * 8];
#pragma unroll
        for (int ni = 0; ni < 4; ni++) {
            float lo, hi;
            upk2(acc[mi][ni], lo, hi);
            float2 v = make_float2(lo + bv[2 * ni], hi + bv[2 * ni + 1]);
            *(float2*)&orow[2 * ni] = v;
        }
    }
}

// ---------------- kernel 3: the recurrence (dataflow-synced) ----------------
// 16 clusters x 8 CTAs. Cluster c owns batches [4c,4c+4). CTA rank r owns units
// [32r,32r+32) with weights in registers. h is triple-buffered in every CTA's
// smem; producers broadcast via st.async (tx-counted on the receiver's mbarrier);
// each CTA waits only for its own 4KB/step of incoming h. No cluster barrier in loop.
__global__ void __launch_bounds__(512, 1) __cluster_dims__(8, 1, 1)
rec_kernel(float* __restrict__ out) {
    __shared__ __align__(16) float h_s[3][4][NU];            // 12 KB
    __shared__ __align__(16) float red_s[8][8][32];          // [b*2+m][kc][u] 8 KB
    __shared__ __align__(8)  unsigned long long mbars[3];

    int tid = threadIdx.x;
    int u   = tid & 31;              // lane = unit within CTA slice
    int wid = tid >> 5;              // 16 warps
    int kc  = wid & 7;               // k-chunk 0..7 (32 k each)
    int bh  = wid >> 3;              // batch half 0..1 (2 batches each)
    unsigned rank;
    asm("mov.u32 %0, %%cluster_ctarank;" : "=r"(rank));
    int bg = (int)(blockIdx.x >> 3);
    int ug = (int)rank * 32 + u;
    int k0 = kc * 32;

    // Weight slices in registers as native k-pairs (f32x2).
    // wA[i] covers k = k0+2i, k0+2i+1.
    unsigned long long wA[16], wW[16];
    {
        const unsigned long long* pA = (const unsigned long long*)(g_AeT + (size_t)ug * NU + k0);
        const unsigned long long* pW = (const unsigned long long*)(g_WT  + (size_t)ug * NU + k0);
#pragma unroll
        for (int i = 0; i < 16; i++) { wA[i] = pA[i]; wW[i] = pW[i]; }
    }

    // Init: zero read buffer 0, init mbarriers, pre-arm bufs 1 and 2
    for (int i = tid; i < 4 * NU; i += 512) ((float*)h_s[0])[i] = 0.0f;
    unsigned mb = su32(&mbars[0]);
    if (tid == 0) {
        mbar_init(mb + 0, 1);
        mbar_init(mb + 8, 1);
        mbar_init(mb + 16, 1);
        mbar_expect(mb + 8, 4096);
        mbar_expect(mb + 16, 4096);
    }
    __syncthreads();
    asm volatile("barrier.cluster.arrive.aligned;" ::: "memory");
    asm volatile("barrier.cluster.wait.aligned;" ::: "memory");

    // Consumer setup (first 128 threads: one (cb, cu) output each)
    int cb = tid >> 5;
    int cu = tid & 31;
    const float* xu_p = g_xu + ((size_t)(bg * 4 + cb)) * TS * NU + ((int)rank * 32 + cu);
    float* out_p      = out  + ((size_t)(bg * 4 + cb)) * TS * NU + ((int)rank * 32 + cu);

    // Remote base addresses (h_s[0][0][0]) for all 8 cluster ranks
    unsigned ra8[8];
    unsigned h0 = su32(&h_s[0][0][0]);
    unsigned mdel = mb - h0;   // offset of mbars relative to h_s base (same in all CTAs)
#pragma unroll
    for (int r = 0; r < 8; r++) {
        asm("mapa.shared::cluster.u32 %0, %1, %2;" : "=r"(ra8[r]) : "r"(h0), "r"(r));
    }

    unsigned ph0 = 0, ph1 = 0, ph2 = 0;
    int b0 = bh * 2;

#define DO_STEP(RB, WB, PH, DOWAIT, T)                                              \
    {                                                                               \
        if (DOWAIT) { mbar_wait(mb + 8 * (RB), (PH)); }                             \
        if (tid == 0) mbar_expect(mb + 8 * (RB), 4096);                             \
        float xu_v = 0.0f;                                                          \
        if (tid < 128) xu_v = __ldg(xu_p + (size_t)(T) * NU);                       \
        unsigned long long accA0 = 0, accW0 = 0, accA1 = 0, accW1 = 0;              \
        {                                                                           \
            const ulonglong2* hp0 = (const ulonglong2*)&h_s[RB][b0][k0];            \
            const ulonglong2* hp1 = (const ulonglong2*)&h_s[RB][b0 + 1][k0];        \
            _Pragma("unroll")                                                       \
            for (int j = 0; j < 4; j++) {                                           \
                ulonglong2 v0 = hp0[j];                                             \
                ulonglong2 v1 = hp1[j];                                             \
                accA0 = fma2(wA[2 * j + 0], v0.x, accA0);                           \
                accW0 = fma2(wW[2 * j + 0], v0.x, accW0);                           \
                accA1 = fma2(wA[2 * j + 0], v1.x, accA1);                           \
                accW1 = fma2(wW[2 * j + 0], v1.x, accW1);                           \
                accA0 = fma2(wA[2 * j + 1], v0.y, accA0);                           \
                accW0 = fma2(wW[2 * j + 1], v0.y, accW0);                           \
                accA1 = fma2(wA[2 * j + 1], v1.y, accA1);                           \
                accW1 = fma2(wW[2 * j + 1], v1.y, accW1);                           \
            }                                                                       \
            const ulonglong2* hq0 = hp0 + 4;                                        \
            const ulonglong2* hq1 = hp1 + 4;                                        \
            _Pragma("unroll")                                                       \
            for (int j = 0; j < 4; j++) {                                           \
                ulonglong2 v0 = hq0[j];                                             \
                ulonglong2 v1 = hq1[j];                                             \
                accA0 = fma2(wA[2 * j + 8], v0.x, accA0);                           \
                accW0 = fma2(wW[2 * j + 8], v0.x, accW0);                           \
                accA1 = fma2(wA[2 * j + 8], v1.x, accA1);                           \
                accW1 = fma2(wW[2 * j + 8], v1.x, accW1);                           \
                accA0 = fma2(wA[2 * j + 9], v0.y, accA0);                           \
                accW0 = fma2(wW[2 * j + 9], v0.y, accW0);                           \
                accA1 = fma2(wA[2 * j + 9], v1.y, accA1);                           \
                accW1 = fma2(wW[2 * j + 9], v1.y, accW1);                           \
            }                                                                       \
        }                                                                           \
        {                                                                           \
            float lo, hi;                                                           \
            upk2(accA0, lo, hi); red_s[b0 * 2 + 0][kc][u] = lo + hi;                \
            upk2(accW0, lo, hi); red_s[b0 * 2 + 1][kc][u] = lo + hi;                \
            upk2(accA1, lo, hi); red_s[b0 * 2 + 2][kc][u] = lo + hi;                \
            upk2(accW1, lo, hi); red_s[b0 * 2 + 3][kc][u] = lo + hi;                \
        }                                                                           \
        __syncthreads();                                                            \
        if (tid < 128) {                                                            \
            float sA0 = 0, sA1 = 0, sW0 = 0, sW1 = 0;                               \
            _Pragma("unroll")                                                       \
            for (int j = 0; j < 4; j++) {                                           \
                sA0 += red_s[cb * 2 + 0][2 * j + 0][cu];                            \
                sA1 += red_s[cb * 2 + 0][2 * j + 1][cu];                            \
                sW0 += red_s[cb * 2 + 1][2 * j + 0][cu];                            \
                sW1 += red_s[cb * 2 + 1][2 * j + 1][cu];                            \
            }                                                                       \
            float hold = h_s[RB][cb][ug];                                           \
            float hnew = hold + (sA0 + sA1) + EPSF * tanhf((sW0 + sW1) + xu_v);     \
            out_p[(size_t)(T) * NU] = hnew;                                         \
            unsigned doff = (unsigned)(((WB) * 4 + cb) * NU + ug) * 4u;             \
            unsigned moff = mdel + 8u * (WB);                                       \
            _Pragma("unroll")                                                       \
            for (int r = 0; r < 8; r++) {                                           \
                st_async_remote(ra8[r] + doff, hnew, ra8[r] + moff);                \
            }                                                                       \
        }                                                                           \
    }

    // step 0 (reads pre-zeroed buffer 0, no wait)
    DO_STEP(0, 1, ph0, false, 0);
    int t = 1;
    while (t < TS) {
        DO_STEP(1, 2, ph1, true, t); ph1 ^= 1; t++;
        if (t < TS) { DO_STEP(2, 0, ph2, true, t); ph2 ^= 1; t++; }
        if (t < TS) { DO_STEP(0, 1, ph0, true, t); ph0 ^= 1; t++; }
    }
#undef DO_STEP

    // Drain: wait for the final step's incoming stores (buf 2) so no CTA exits
    // while peers' st.async into this CTA's smem are in flight.
    mbar_wait(mb + 16, ph2);
    asm volatile("barrier.cluster.arrive.aligned;" ::: "memory");
    asm volatile("barrier.cluster.wait.aligned;" ::: "memory");
}

extern "C" void kernel_launch(void* const* d_in, const int* in_sizes, int n_in,
                              void* d_out, int out_size) {
    const float* x = (const float*)d_in[0];
    const float* C = (const float*)d_in[1];
    const float* B = (const float*)d_in[2];
    const float* U = (const float*)d_in[3];
    const float* b = (const float*)d_in[4];
    float* out = (float*)d_out;

    prep_kernel<<<NU, NU>>>(C, B);
    xu_kernel<<<dim3((NB * TS) / 128, NU / 128), 256>>>(x, U, b);
    rec_kernel<<<128, 512>>>(out);
}